// round 12
// baseline (speedup 1.0000x reference)
#include <cuda_runtime.h>
#include <cuda_fp16.h>

#define BB 2
#define SS 2048
#define DD 256
#define HH 8
#define DHD 32

// Scratch (allocation-free: device globals)
__device__ float g_q[BB*HH*SS*DHD];
__device__ float g_k[BB*HH*SS*DHD];
__device__ float g_v[BB*HH*SS*DHD];
__device__ float g_ctx[BB*SS*DD];

// ---------------------------------------------------------------------------
// mma helpers
// ---------------------------------------------------------------------------
__device__ __forceinline__ unsigned f2tf(float f) {
    unsigned u;
    asm("cvt.rna.tf32.f32 %0, %1;" : "=r"(u) : "f"(f));
    return u;
}

__device__ __forceinline__ void mma_tf32(float c[4], const unsigned a[4],
                                         unsigned b0, unsigned b1) {
    asm volatile(
        "mma.sync.aligned.m16n8k8.row.col.f32.tf32.tf32.f32 "
        "{%0,%1,%2,%3},{%4,%5,%6,%7},{%8,%9},{%0,%1,%2,%3};"
        : "+f"(c[0]), "+f"(c[1]), "+f"(c[2]), "+f"(c[3])
        : "r"(a[0]), "r"(a[1]), "r"(a[2]), "r"(a[3]), "r"(b0), "r"(b1));
}

__device__ __forceinline__ void mma_f16(float c[4], const unsigned a[4],
                                        unsigned b0, unsigned b1) {
    asm volatile(
        "mma.sync.aligned.m16n8k16.row.col.f32.f16.f16.f32 "
        "{%0,%1,%2,%3},{%4,%5,%6,%7},{%8,%9},{%0,%1,%2,%3};"
        : "+f"(c[0]), "+f"(c[1]), "+f"(c[2]), "+f"(c[3])
        : "r"(a[0]), "r"(a[1]), "r"(a[2]), "r"(a[3]), "r"(b0), "r"(b1));
}

__device__ __forceinline__ float2 h2f(unsigned u) {
    return __half22float2(*(__half2*)&u);
}

// ---------------------------------------------------------------------------
// QKV projection (unchanged)
// ---------------------------------------------------------------------------
__global__ __launch_bounds__(256) void qkv_kernel(
    const float* __restrict__ x,
    const float* __restrict__ wq, const float* __restrict__ bq,
    const float* __restrict__ wk, const float* __restrict__ bk,
    const float* __restrict__ wv, const float* __restrict__ bv)
{
    __shared__ float As[32][68];
    __shared__ float Bs[32][68];
    const int mt = blockIdx.x * 64;
    const int nt = blockIdx.y * 64;
    const int wsel = nt >> 8;
    const int nw = nt & 255;
    const float* W    = (wsel == 0) ? wq : ((wsel == 1) ? wk : wv);
    const float* bias = (wsel == 0) ? bq : ((wsel == 1) ? bk : bv);
    float* dst        = (wsel == 0) ? g_q : ((wsel == 1) ? g_k : g_v);

    const int tid = threadIdx.x;
    const int ty = tid >> 4, tx = tid & 15;
    float acc[4][4] = {};

    for (int k0 = 0; k0 < 256; k0 += 32) {
        for (int t = tid; t < 64 * 32; t += 256) {
            int m = t >> 5, kk = t & 31;
            As[kk][m] = x[(size_t)(mt + m) * 256 + k0 + kk];
            Bs[kk][m] = W[(size_t)(nw + m) * 256 + k0 + kk];
        }
        __syncthreads();
        #pragma unroll
        for (int kk = 0; kk < 32; kk++) {
            float4 a4 = *(const float4*)&As[kk][ty * 4];
            float4 b4 = *(const float4*)&Bs[kk][tx * 4];
            float a[4] = {a4.x, a4.y, a4.z, a4.w};
            float b[4] = {b4.x, b4.y, b4.z, b4.w};
            #pragma unroll
            for (int i = 0; i < 4; i++)
                #pragma unroll
                for (int j = 0; j < 4; j++)
                    acc[i][j] += a[i] * b[j];
        }
        __syncthreads();
    }
    #pragma unroll
    for (int i = 0; i < 4; i++) {
        int m = mt + ty * 4 + i;
        int bidx = m >> 11, s = m & 2047;
        #pragma unroll
        for (int j = 0; j < 4; j++) {
            int n = nw + tx * 4 + j;
            int h = n >> 5, dh = n & 31;
            dst[(((size_t)(bidx * HH + h) * SS + s) * DHD) + dh] = acc[i][j] + bias[n];
        }
    }
}

// ---------------------------------------------------------------------------
// Output projection (unchanged)
// ---------------------------------------------------------------------------
__global__ __launch_bounds__(256) void proj_kernel(
    const float* __restrict__ wc, const float* __restrict__ bc,
    float* __restrict__ out)
{
    __shared__ float As[32][68];
    __shared__ float Bs[32][68];
    const int mt = blockIdx.x * 64;
    const int nw = blockIdx.y * 64;
    const int tid = threadIdx.x;
    const int ty = tid >> 4, tx = tid & 15;
    float acc[4][4] = {};

    for (int k0 = 0; k0 < 256; k0 += 32) {
        for (int t = tid; t < 64 * 32; t += 256) {
            int m = t >> 5, kk = t & 31;
            As[kk][m] = g_ctx[(size_t)(mt + m) * 256 + k0 + kk];
            Bs[kk][m] = wc[(size_t)(nw + m) * 256 + k0 + kk];
        }
        __syncthreads();
        #pragma unroll
        for (int kk = 0; kk < 32; kk++) {
            float4 a4 = *(const float4*)&As[kk][ty * 4];
            float4 b4 = *(const float4*)&Bs[kk][tx * 4];
            float a[4] = {a4.x, a4.y, a4.z, a4.w};
            float b[4] = {b4.x, b4.y, b4.z, b4.w};
            #pragma unroll
            for (int i = 0; i < 4; i++)
                #pragma unroll
                for (int j = 0; j < 4; j++)
                    acc[i][j] += a[i] * b[j];
        }
        __syncthreads();
    }
    #pragma unroll
    for (int i = 0; i < 4; i++) {
        int m = mt + ty * 4 + i;
        #pragma unroll
        for (int j = 0; j < 4; j++) {
            int n = nw + tx * 4 + j;
            out[(size_t)m * 256 + n] = acc[i][j] + bc[n];
        }
    }
}

// ---------------------------------------------------------------------------
// Attention v3: fp16 score storage + fp16 mma scores + tf32 mma PV.
// smem (bytes):
//   sS    [16][2056] fp16  = 65792   scores/probs
//   alias [40960]           K fp16 [512][40]  (scores phase)
//                           V fp32 [256][32] XOR-swizzled (PV phase)
//                           sRed fp32 [8][512] (reduction)
//   sQ    [16][40] fp16   = 1280
// total 108032 -> 2 CTAs/SM, grid 256 = single wave.
// ---------------------------------------------------------------------------
#define SSH 2056
#define SMEM_BYTES (16*SSH*2 + 40960 + 16*40*2)

__global__ __launch_bounds__(256, 2) void attn_kernel(float* __restrict__ attn_out)
{
    extern __shared__ char sm[];
    __half* sS = (__half*)sm;                        // 16 x 2056
    char*   sAlias = sm + 16 * SSH * 2;
    __half* sK = (__half*)sAlias;                    // 512 x 40 (stride 40 halfs)
    float*  sV = (float*)sAlias;                     // 256 x 32 XOR swizzled
    __half* sQ = (__half*)(sAlias + 40960);          // 16 x 40
    __shared__ float s_invl[16];

    const int tid  = threadIdx.x;
    const int w    = tid >> 5;       // warp 0..7
    const int lane = tid & 31;
    const int g    = lane >> 2;      // 0..7
    const int tg   = lane & 3;       // 0..3
    const int b  = blockIdx.x >> 7;
    const int q0 = (blockIdx.x & 127) << 4;

    float* ap = attn_out + (size_t)(b * SS + q0) * SS;

    for (int h = 0; h < HH; h++) {
        const float* qb = g_q + ((size_t)(b * HH + h) * SS + q0) * DHD;
        const float* kb = g_k + (size_t)(b * HH + h) * SS * DHD;
        const float* vb = g_v + (size_t)(b * HH + h) * SS * DHD;

        // --- load Q tile (16x32), pre-scale by 1/sqrt(32), convert fp16 ---
        const float scale = 0.17677669529663687f;
        for (int t = tid; t < 16 * 32; t += 256)
            sQ[(t >> 5) * 40 + (t & 31)] = __float2half(qb[t] * scale);

        // --- scores: S = Q K^T via fp16 mma, 4 k-tiles of 512 keys ---
        unsigned qa[2][4];
        for (int kt = 0; kt < 4; kt++) {
            __syncthreads();   // prior alias-buffer consumers done; kt==0: sQ ready
            for (int t = tid; t < 4096; t += 256) {
                int row = t >> 3, gd = t & 7;
                float4 v = *(const float4*)(kb + (size_t)kt * 16384 + row * 32 + gd * 4);
                __half2* dst = (__half2*)(sK + row * 40 + gd * 4);
                dst[0] = __floats2half2_rn(v.x, v.y);
                dst[1] = __floats2half2_rn(v.z, v.w);
            }
            __syncthreads();
            if (kt == 0) {
                #pragma unroll
                for (int kc = 0; kc < 2; kc++) {
                    qa[kc][0] = *(const unsigned*)(sQ + g * 40 + kc * 16 + 2 * tg);
                    qa[kc][1] = *(const unsigned*)(sQ + (g + 8) * 40 + kc * 16 + 2 * tg);
                    qa[kc][2] = *(const unsigned*)(sQ + g * 40 + kc * 16 + 2 * tg + 8);
                    qa[kc][3] = *(const unsigned*)(sQ + (g + 8) * 40 + kc * 16 + 2 * tg + 8);
                }
            }
            const int n0w = w * 64;
            #pragma unroll
            for (int nt = 0; nt < 8; nt++) {
                const int n0 = n0w + nt * 8;
                const __half* krow = sK + (n0 + g) * 40;
                float c[4] = {0.f, 0.f, 0.f, 0.f};
                #pragma unroll
                for (int kc = 0; kc < 2; kc++) {
                    unsigned b0 = *(const unsigned*)(krow + kc * 16 + 2 * tg);
                    unsigned b1 = *(const unsigned*)(krow + kc * 16 + 2 * tg + 8);
                    mma_f16(c, qa[kc], b0, b1);
                }
                const int col = kt * 512 + n0 + tg * 2;
                *(__half2*)(sS + g * SSH + col)       = __floats2half2_rn(c[0], c[1]);
                *(__half2*)(sS + (g + 8) * SSH + col) = __floats2half2_rn(c[2], c[3]);
            }
        }
        __syncthreads();

        // --- softmax over full row (fp32 math, fp16 storage) ---
        {
            const int row = tid >> 4, j = tid & 15;   // 16 threads per row
            uint4* r4 = (uint4*)(sS + (size_t)row * SSH);   // 256 uint4 per row
            float mx = -1e30f;
            for (int k = j; k < 256; k += 16) {
                uint4 u = r4[k];
                float2 f0 = h2f(u.x), f1 = h2f(u.y), f2 = h2f(u.z), f3 = h2f(u.w);
                mx = fmaxf(mx, fmaxf(fmaxf(f0.x, f0.y), fmaxf(f1.x, f1.y)));
                mx = fmaxf(mx, fmaxf(fmaxf(f2.x, f2.y), fmaxf(f3.x, f3.y)));
            }
            #pragma unroll
            for (int o = 8; o; o >>= 1) mx = fmaxf(mx, __shfl_xor_sync(0xffffffffu, mx, o));
            float sum = 0.f;
            for (int k = j; k < 256; k += 16) {
                uint4 u = r4[k];
                float2 f0 = h2f(u.x), f1 = h2f(u.y), f2 = h2f(u.z), f3 = h2f(u.w);
                f0.x = __expf(f0.x - mx); f0.y = __expf(f0.y - mx);
                f1.x = __expf(f1.x - mx); f1.y = __expf(f1.y - mx);
                f2.x = __expf(f2.x - mx); f2.y = __expf(f2.y - mx);
                f3.x = __expf(f3.x - mx); f3.y = __expf(f3.y - mx);
                sum += (f0.x + f0.y) + (f1.x + f1.y) + (f2.x + f2.y) + (f3.x + f3.y);
                __half2 h0 = __floats2half2_rn(f0.x, f0.y);
                __half2 h1 = __floats2half2_rn(f1.x, f1.y);
                __half2 h2v = __floats2half2_rn(f2.x, f2.y);
                __half2 h3 = __floats2half2_rn(f3.x, f3.y);
                u.x = *(unsigned*)&h0; u.y = *(unsigned*)&h1;
                u.z = *(unsigned*)&h2v; u.w = *(unsigned*)&h3;
                r4[k] = u;
            }
            #pragma unroll
            for (int o = 8; o; o >>= 1) sum += __shfl_xor_sync(0xffffffffu, sum, o);
            if (j == 0) s_invl[row] = 1.0f / sum;
        }
        __syncthreads();

        // --- accumulate head-mean attention into d_out slice ---
        {
            float4* a4 = (float4*)ap;
            for (int t = tid; t < 16 * 512; t += 256) {
                int r = t >> 9, c4 = t & 511;
                uint2 u = *(const uint2*)(sS + (size_t)r * SSH + c4 * 4);
                float2 p0 = h2f(u.x), p1 = h2f(u.y);
                float f = s_invl[r] * 0.125f;
                float4 v = make_float4(p0.x * f, p0.y * f, p1.x * f, p1.y * f);
                if (h == 0) {
                    a4[r * 512 + c4] = v;
                } else {
                    float4 o = a4[r * 512 + c4];
                    o.x += v.x; o.y += v.y; o.z += v.z; o.w += v.w;
                    a4[r * 512 + c4] = o;
                }
            }
        }

        // --- PV: O = P V via tf32 mma, 8 phases of 256 k ---
        float oc[4][4] = {};
        const int gdb = g >> 2, gi = g & 3;
        for (int p = 0; p < 8; p++) {
            __syncthreads();   // previous phase alias consumers done
            for (int t = tid; t < 2048; t += 256) {
                int row = t >> 3, gd = t & 7;
                float4 v = *(const float4*)(vb + (size_t)p * 8192 + row * 32 + gd * 4);
                float* pp = &sV[row * 32 + ((gd ^ (row & 7)) << 2)];
                pp[0] = __uint_as_float(f2tf(v.x));
                pp[1] = __uint_as_float(f2tf(v.y));
                pp[2] = __uint_as_float(f2tf(v.z));
                pp[3] = __uint_as_float(f2tf(v.w));
            }
            __syncthreads();
            #pragma unroll
            for (int j4 = 0; j4 < 4; j4++) {
                const int kc  = w * 4 + j4;          // 0..31 within phase
                const int kr  = kc * 8;              // local V row base
                const int ksg = p * 256 + kr;        // sS column base
                unsigned pa[4];
                pa[0] = f2tf(__half2float(sS[g * SSH + ksg + tg]));
                pa[1] = f2tf(__half2float(sS[(g + 8) * SSH + ksg + tg]));
                pa[2] = f2tf(__half2float(sS[g * SSH + ksg + tg + 4]));
                pa[3] = f2tf(__half2float(sS[(g + 8) * SSH + ksg + tg + 4]));
                #pragma unroll
                for (int nt = 0; nt < 4; nt++) {
                    const int gd = nt * 2 + gdb;
                    unsigned b0 = __float_as_uint(
                        sV[(kr + tg) * 32 + ((gd ^ tg) << 2) + gi]);
                    unsigned b1 = __float_as_uint(
                        sV[(kr + tg + 4) * 32 + ((gd ^ (tg + 4)) << 2) + gi]);
                    mma_tf32(oc[nt], pa, b0, b1);
                }
            }
        }
        __syncthreads();   // last phase consumers done before sRed overwrites sV

        // --- cross-warp reduction of the 8 k-partials via smem ---
        float* sRed = sV;   // 8 * 512 floats
        #pragma unroll
        for (int nt = 0; nt < 4; nt++) {
            const int col = nt * 8 + tg * 2;
            sRed[w * 512 + g * 32 + col]           = oc[nt][0];
            sRed[w * 512 + g * 32 + col + 1]       = oc[nt][1];
            sRed[w * 512 + (g + 8) * 32 + col]     = oc[nt][2];
            sRed[w * 512 + (g + 8) * 32 + col + 1] = oc[nt][3];
        }
        __syncthreads();
        for (int o = tid; o < 512; o += 256) {
            int r = o >> 5, d = o & 31;
            float s = 0.f;
            #pragma unroll
            for (int e = 0; e < 8; e++) s += sRed[e * 512 + o];
            g_ctx[(size_t)(b * SS + q0 + r) * DD + h * DHD + d] = s * s_invl[r];
        }
        __syncthreads();   // protect sRed/sQ/sS before next head
    }
}

// ---------------------------------------------------------------------------
extern "C" void kernel_launch(void* const* d_in, const int* in_sizes, int n_in,
                              void* d_out, int out_size)
{
    const float* x  = (const float*)d_in[0];
    const float* wq = (const float*)d_in[1];
    const float* bq = (const float*)d_in[2];
    const float* wk = (const float*)d_in[3];
    const float* bk = (const float*)d_in[4];
    const float* wv = (const float*)d_in[5];
    const float* bv = (const float*)d_in[6];
    const float* wc = (const float*)d_in[7];
    const float* bc = (const float*)d_in[8];

    float* out  = (float*)d_out;
    float* attn = out + (size_t)BB * SS * DD;

    qkv_kernel<<<dim3(64, 12), 256>>>(x, wq, bq, wk, bk, wv, bv);

    cudaFuncSetAttribute(attn_kernel,
                         cudaFuncAttributeMaxDynamicSharedMemorySize,
                         SMEM_BYTES);
    attn_kernel<<<256, 256, SMEM_BYTES>>>(attn);

    proj_kernel<<<dim3(64, 4), 256>>>(wc, bc, out);
}

// round 13
// speedup vs baseline: 1.2075x; 1.2075x over previous
#include <cuda_runtime.h>
#include <cuda_fp16.h>

#define BB 2
#define SS 2048
#define DD 256
#define HH 8
#define DHD 32

// Scratch (allocation-free: device globals). q/k/v now fp16.
__device__ __half g_q[BB*HH*SS*DHD];
__device__ __half g_k[BB*HH*SS*DHD];
__device__ __half g_v[BB*HH*SS*DHD];
__device__ float  g_ctx[BB*SS*DD];

// ---------------------------------------------------------------------------
// mma / ldmatrix helpers
// ---------------------------------------------------------------------------
__device__ __forceinline__ void mma_f16(float c[4], const unsigned a[4],
                                        unsigned b0, unsigned b1) {
    asm volatile(
        "mma.sync.aligned.m16n8k16.row.col.f32.f16.f16.f32 "
        "{%0,%1,%2,%3},{%4,%5,%6,%7},{%8,%9},{%0,%1,%2,%3};"
        : "+f"(c[0]), "+f"(c[1]), "+f"(c[2]), "+f"(c[3])
        : "r"(a[0]), "r"(a[1]), "r"(a[2]), "r"(a[3]), "r"(b0), "r"(b1));
}

__device__ __forceinline__ void ldsm_x2_t(unsigned& r0, unsigned& r1, const void* p) {
    unsigned addr = (unsigned)__cvta_generic_to_shared(p);
    asm volatile("ldmatrix.sync.aligned.m8n8.x2.trans.shared.b16 {%0,%1}, [%2];"
                 : "=r"(r0), "=r"(r1) : "r"(addr));
}

__device__ __forceinline__ float2 h2f(unsigned u) {
    return __half22float2(*(__half2*)&u);
}

// ---------------------------------------------------------------------------
// QKV projection, 8x8 register micro-tile. BM=128, BN=128, BK=16.
// Writes fp16 head-major [B,H,S,32].
// ---------------------------------------------------------------------------
__global__ __launch_bounds__(256, 2) void qkv_kernel(
    const float* __restrict__ x,
    const float* __restrict__ wq, const float* __restrict__ bq,
    const float* __restrict__ wk, const float* __restrict__ bk,
    const float* __restrict__ wv, const float* __restrict__ bv)
{
    __shared__ float As[16][132];
    __shared__ float Bs[16][132];
    const int mt = blockIdx.x * 128;
    const int by = blockIdx.y;            // 0..5
    const int wsel = by >> 1;             // 0=q,1=k,2=v
    const int nw = (by & 1) * 128;
    const float* W    = (wsel == 0) ? wq : ((wsel == 1) ? wk : wv);
    const float* bias = (wsel == 0) ? bq : ((wsel == 1) ? bk : bv);
    __half* dst       = (wsel == 0) ? g_q : ((wsel == 1) ? g_k : g_v);

    const int tid = threadIdx.x;
    const int ty = tid >> 4, tx = tid & 15;
    const int lm = tid >> 1;               // staging row 0..127
    const int lq = (tid & 1) * 8;          // staging k offset 0/8
    float acc[8][8] = {};

    for (int k0 = 0; k0 < 256; k0 += 16) {
        __syncthreads();
        {
            const float* xr = x + (size_t)(mt + lm) * 256 + k0 + lq;
            const float* wr = W + (size_t)(nw + lm) * 256 + k0 + lq;
            float4 a0 = *(const float4*)xr;
            float4 a1 = *(const float4*)(xr + 4);
            float4 b0 = *(const float4*)wr;
            float4 b1 = *(const float4*)(wr + 4);
            As[lq+0][lm] = a0.x; As[lq+1][lm] = a0.y; As[lq+2][lm] = a0.z; As[lq+3][lm] = a0.w;
            As[lq+4][lm] = a1.x; As[lq+5][lm] = a1.y; As[lq+6][lm] = a1.z; As[lq+7][lm] = a1.w;
            Bs[lq+0][lm] = b0.x; Bs[lq+1][lm] = b0.y; Bs[lq+2][lm] = b0.z; Bs[lq+3][lm] = b0.w;
            Bs[lq+4][lm] = b1.x; Bs[lq+5][lm] = b1.y; Bs[lq+6][lm] = b1.z; Bs[lq+7][lm] = b1.w;
        }
        __syncthreads();
        #pragma unroll
        for (int kk = 0; kk < 16; kk++) {
            float a[8], b[8];
            *(float4*)&a[0] = *(const float4*)&As[kk][ty * 8];
            *(float4*)&a[4] = *(const float4*)&As[kk][ty * 8 + 4];
            *(float4*)&b[0] = *(const float4*)&Bs[kk][tx * 8];
            *(float4*)&b[4] = *(const float4*)&Bs[kk][tx * 8 + 4];
            #pragma unroll
            for (int i = 0; i < 8; i++)
                #pragma unroll
                for (int j = 0; j < 8; j++)
                    acc[i][j] += a[i] * b[j];
        }
    }
    #pragma unroll
    for (int i = 0; i < 8; i++) {
        int m = mt + ty * 8 + i;
        int bidx = m >> 11, s = m & 2047;
        #pragma unroll
        for (int j = 0; j < 8; j += 2) {
            int n = nw + tx * 8 + j;
            int h = n >> 5, dh = n & 31;
            __half2 hv = __floats2half2_rn(acc[i][j] + bias[n], acc[i][j+1] + bias[n+1]);
            *(__half2*)&dst[(((size_t)(bidx * HH + h) * SS + s) * DHD) + dh] = hv;
        }
    }
}

// ---------------------------------------------------------------------------
// Output projection, 8x8 micro-tile: out = ctx @ wc^T + bc. BM=128, BN=128.
// ---------------------------------------------------------------------------
__global__ __launch_bounds__(256, 2) void proj_kernel(
    const float* __restrict__ wc, const float* __restrict__ bc,
    float* __restrict__ out)
{
    __shared__ float As[16][132];
    __shared__ float Bs[16][132];
    const int mt = blockIdx.x * 128;
    const int nw = blockIdx.y * 128;
    const int tid = threadIdx.x;
    const int ty = tid >> 4, tx = tid & 15;
    const int lm = tid >> 1;
    const int lq = (tid & 1) * 8;
    float acc[8][8] = {};

    for (int k0 = 0; k0 < 256; k0 += 16) {
        __syncthreads();
        {
            const float* xr = g_ctx + (size_t)(mt + lm) * 256 + k0 + lq;
            const float* wr = wc + (size_t)(nw + lm) * 256 + k0 + lq;
            float4 a0 = *(const float4*)xr;
            float4 a1 = *(const float4*)(xr + 4);
            float4 b0 = *(const float4*)wr;
            float4 b1 = *(const float4*)(wr + 4);
            As[lq+0][lm] = a0.x; As[lq+1][lm] = a0.y; As[lq+2][lm] = a0.z; As[lq+3][lm] = a0.w;
            As[lq+4][lm] = a1.x; As[lq+5][lm] = a1.y; As[lq+6][lm] = a1.z; As[lq+7][lm] = a1.w;
            Bs[lq+0][lm] = b0.x; Bs[lq+1][lm] = b0.y; Bs[lq+2][lm] = b0.z; Bs[lq+3][lm] = b0.w;
            Bs[lq+4][lm] = b1.x; Bs[lq+5][lm] = b1.y; Bs[lq+6][lm] = b1.z; Bs[lq+7][lm] = b1.w;
        }
        __syncthreads();
        #pragma unroll
        for (int kk = 0; kk < 16; kk++) {
            float a[8], b[8];
            *(float4*)&a[0] = *(const float4*)&As[kk][ty * 8];
            *(float4*)&a[4] = *(const float4*)&As[kk][ty * 8 + 4];
            *(float4*)&b[0] = *(const float4*)&Bs[kk][tx * 8];
            *(float4*)&b[4] = *(const float4*)&Bs[kk][tx * 8 + 4];
            #pragma unroll
            for (int i = 0; i < 8; i++)
                #pragma unroll
                for (int j = 0; j < 8; j++)
                    acc[i][j] += a[i] * b[j];
        }
    }
    #pragma unroll
    for (int i = 0; i < 8; i++) {
        int m = mt + ty * 8 + i;
        #pragma unroll
        for (int j = 0; j < 8; j++) {
            int n = nw + tx * 8 + j;
            out[(size_t)m * 256 + n] = acc[i][j] + bc[n];
        }
    }
}

// ---------------------------------------------------------------------------
// Attention v4: fp16 everywhere on the tensor path.
//   scores: fp16 mma (K staged fp16, stride-40 rows)
//   PV:     fp16 mma (V staged fp16, B-frag via ldmatrix.x2.trans)
// smem (bytes):
//   sS    [16][2056] fp16 = 65792
//   alias 40960: K fp16 [512][40] | V fp16 [256][40] | sRed fp32 [8][512]
//   sQ    [16][40] fp16 = 1280          total 108032 -> 2 CTAs/SM
// ---------------------------------------------------------------------------
#define SSH 2056
#define SMEM_BYTES (16*SSH*2 + 40960 + 16*40*2)

__global__ __launch_bounds__(256, 2) void attn_kernel(float* __restrict__ attn_out)
{
    extern __shared__ char sm[];
    __half* sS = (__half*)sm;                        // 16 x 2056
    char*   sAlias = sm + 16 * SSH * 2;
    __half* sK  = (__half*)sAlias;                   // 512 x 40
    __half* sVh = (__half*)sAlias;                   // 256 x 40
    float*  sRd = (float*)sAlias;                    // 8 x 512
    __half* sQ  = (__half*)(sAlias + 40960);         // 16 x 40
    __shared__ float s_invl[16];

    const int tid  = threadIdx.x;
    const int w    = tid >> 5;
    const int lane = tid & 31;
    const int g    = lane >> 2;
    const int tg   = lane & 3;
    const int b  = blockIdx.x >> 7;
    const int q0 = (blockIdx.x & 127) << 4;

    float* ap = attn_out + (size_t)(b * SS + q0) * SS;

    for (int h = 0; h < HH; h++) {
        const __half* qb = g_q + ((size_t)(b * HH + h) * SS + q0) * DHD;
        const __half* kb = g_k + (size_t)(b * HH + h) * SS * DHD;
        const __half* vb = g_v + (size_t)(b * HH + h) * SS * DHD;

        // --- Q tile (16x32), scale by 1/sqrt(32), fp16 ---
        const float scale = 0.17677669529663687f;
        {
            int r = tid >> 4, c2 = (tid & 15) * 2;
            float2 f = __half22float2(*(const __half2*)(qb + r * 32 + c2));
            *(__half2*)(sQ + r * 40 + c2) = __floats2half2_rn(f.x * scale, f.y * scale);
        }

        // --- scores: S = Q K^T via fp16 mma, 4 k-tiles of 512 keys ---
        unsigned qa[2][4];
        for (int kt = 0; kt < 4; kt++) {
            __syncthreads();   // prior alias consumers done; kt==0: sQ ready
            #pragma unroll
            for (int it = 0; it < 8; it++) {
                int t = it * 256 + tid;
                int row = t >> 2, gd = t & 3;
                uint4 v = *(const uint4*)(kb + (size_t)kt * 16384 + row * 32 + gd * 8);
                *(uint4*)(sK + row * 40 + gd * 8) = v;
            }
            __syncthreads();
            if (kt == 0) {
                #pragma unroll
                for (int kc = 0; kc < 2; kc++) {
                    qa[kc][0] = *(const unsigned*)(sQ + g * 40 + kc * 16 + 2 * tg);
                    qa[kc][1] = *(const unsigned*)(sQ + (g + 8) * 40 + kc * 16 + 2 * tg);
                    qa[kc][2] = *(const unsigned*)(sQ + g * 40 + kc * 16 + 2 * tg + 8);
                    qa[kc][3] = *(const unsigned*)(sQ + (g + 8) * 40 + kc * 16 + 2 * tg + 8);
                }
            }
            const int n0w = w * 64;
            #pragma unroll
            for (int nt = 0; nt < 8; nt++) {
                const int n0 = n0w + nt * 8;
                const __half* krow = sK + (n0 + g) * 40;
                float c[4] = {0.f, 0.f, 0.f, 0.f};
                #pragma unroll
                for (int kc = 0; kc < 2; kc++) {
                    unsigned b0 = *(const unsigned*)(krow + kc * 16 + 2 * tg);
                    unsigned b1 = *(const unsigned*)(krow + kc * 16 + 2 * tg + 8);
                    mma_f16(c, qa[kc], b0, b1);
                }
                const int col = kt * 512 + n0 + tg * 2;
                *(__half2*)(sS + g * SSH + col)       = __floats2half2_rn(c[0], c[1]);
                *(__half2*)(sS + (g + 8) * SSH + col) = __floats2half2_rn(c[2], c[3]);
            }
        }
        __syncthreads();

        // --- softmax (fp32 math, fp16 storage) ---
        {
            const int row = tid >> 4, j = tid & 15;
            uint4* r4 = (uint4*)(sS + (size_t)row * SSH);
            float mx = -1e30f;
            for (int k = j; k < 256; k += 16) {
                uint4 u = r4[k];
                float2 f0 = h2f(u.x), f1 = h2f(u.y), f2 = h2f(u.z), f3 = h2f(u.w);
                mx = fmaxf(mx, fmaxf(fmaxf(f0.x, f0.y), fmaxf(f1.x, f1.y)));
                mx = fmaxf(mx, fmaxf(fmaxf(f2.x, f2.y), fmaxf(f3.x, f3.y)));
            }
            #pragma unroll
            for (int o = 8; o; o >>= 1) mx = fmaxf(mx, __shfl_xor_sync(0xffffffffu, mx, o));
            float sum = 0.f;
            for (int k = j; k < 256; k += 16) {
                uint4 u = r4[k];
                float2 f0 = h2f(u.x), f1 = h2f(u.y), f2 = h2f(u.z), f3 = h2f(u.w);
                f0.x = __expf(f0.x - mx); f0.y = __expf(f0.y - mx);
                f1.x = __expf(f1.x - mx); f1.y = __expf(f1.y - mx);
                f2.x = __expf(f2.x - mx); f2.y = __expf(f2.y - mx);
                f3.x = __expf(f3.x - mx); f3.y = __expf(f3.y - mx);
                sum += (f0.x + f0.y) + (f1.x + f1.y) + (f2.x + f2.y) + (f3.x + f3.y);
                __half2 h0 = __floats2half2_rn(f0.x, f0.y);
                __half2 h1 = __floats2half2_rn(f1.x, f1.y);
                __half2 h2v = __floats2half2_rn(f2.x, f2.y);
                __half2 h3 = __floats2half2_rn(f3.x, f3.y);
                u.x = *(unsigned*)&h0; u.y = *(unsigned*)&h1;
                u.z = *(unsigned*)&h2v; u.w = *(unsigned*)&h3;
                r4[k] = u;
            }
            #pragma unroll
            for (int o = 8; o; o >>= 1) sum += __shfl_xor_sync(0xffffffffu, sum, o);
            if (j == 0) s_invl[row] = 1.0f / sum;
        }
        __syncthreads();

        // --- accumulate head-mean attention into d_out slice ---
        {
            float4* a4 = (float4*)ap;
            for (int t = tid; t < 16 * 512; t += 256) {
                int r = t >> 9, c4 = t & 511;
                uint2 u = *(const uint2*)(sS + (size_t)r * SSH + c4 * 4);
                float2 p0 = h2f(u.x), p1 = h2f(u.y);
                float f = s_invl[r] * 0.125f;
                float4 v = make_float4(p0.x * f, p0.y * f, p1.x * f, p1.y * f);
                if (h == 0) {
                    a4[r * 512 + c4] = v;
                } else {
                    float4 o = a4[r * 512 + c4];
                    o.x += v.x; o.y += v.y; o.z += v.z; o.w += v.w;
                    a4[r * 512 + c4] = o;
                }
            }
        }

        // --- PV via fp16 mma, 8 phases of 256 k; warp owns k-slice w*32..+31 ---
        float oc[4][4] = {};
        for (int p = 0; p < 8; p++) {
            __syncthreads();
            #pragma unroll
            for (int it = 0; it < 4; it++) {
                int t = it * 256 + tid;
                int row = t >> 2, gd = t & 3;
                uint4 v = *(const uint4*)(vb + (size_t)p * 8192 + row * 32 + gd * 8);
                *(uint4*)(sVh + row * 40 + gd * 8) = v;
            }
            __syncthreads();
            #pragma unroll
            for (int j4 = 0; j4 < 2; j4++) {
                const int kr  = w * 32 + j4 * 16;
                const int ksg = p * 256 + kr;
                unsigned pa[4];
                pa[0] = *(const unsigned*)(sS + g * SSH + ksg + 2 * tg);
                pa[1] = *(const unsigned*)(sS + (g + 8) * SSH + ksg + 2 * tg);
                pa[2] = *(const unsigned*)(sS + g * SSH + ksg + 2 * tg + 8);
                pa[3] = *(const unsigned*)(sS + (g + 8) * SSH + ksg + 2 * tg + 8);
                const __half* vrow = sVh + (kr + (lane & 15)) * 40;
                #pragma unroll
                for (int nt = 0; nt < 4; nt++) {
                    unsigned b0, b1;
                    ldsm_x2_t(b0, b1, vrow + nt * 8);
                    mma_f16(oc[nt], pa, b0, b1);
                }
            }
        }
        __syncthreads();   // last phase consumers done before sRd overwrites alias

        // --- cross-warp reduction of the 8 k-partials ---
        #pragma unroll
        for (int nt = 0; nt < 4; nt++) {
            const int col = nt * 8 + tg * 2;
            sRd[w * 512 + g * 32 + col]           = oc[nt][0];
            sRd[w * 512 + g * 32 + col + 1]       = oc[nt][1];
            sRd[w * 512 + (g + 8) * 32 + col]     = oc[nt][2];
            sRd[w * 512 + (g + 8) * 32 + col + 1] = oc[nt][3];
        }
        __syncthreads();
        for (int o = tid; o < 512; o += 256) {
            int r = o >> 5, d = o & 31;
            float s = 0.f;
            #pragma unroll
            for (int e = 0; e < 8; e++) s += sRd[e * 512 + o];
            g_ctx[(size_t)(b * SS + q0 + r) * DD + h * DHD + d] = s * s_invl[r];
        }
        __syncthreads();   // protect alias/sQ/sS before next head
    }
}

// ---------------------------------------------------------------------------
extern "C" void kernel_launch(void* const* d_in, const int* in_sizes, int n_in,
                              void* d_out, int out_size)
{
    const float* x  = (const float*)d_in[0];
    const float* wq = (const float*)d_in[1];
    const float* bq = (const float*)d_in[2];
    const float* wk = (const float*)d_in[3];
    const float* bk = (const float*)d_in[4];
    const float* wv = (const float*)d_in[5];
    const float* bv = (const float*)d_in[6];
    const float* wc = (const float*)d_in[7];
    const float* bc = (const float*)d_in[8];

    float* out  = (float*)d_out;
    float* attn = out + (size_t)BB * SS * DD;

    qkv_kernel<<<dim3(32, 6), 256>>>(x, wq, bq, wk, bk, wv, bv);

    cudaFuncSetAttribute(attn_kernel,
                         cudaFuncAttributeMaxDynamicSharedMemorySize,
                         SMEM_BYTES);
    attn_kernel<<<256, 256, SMEM_BYTES>>>(attn);

    proj_kernel<<<dim3(32, 2), 256>>>(wc, bc, out);
}

// round 14
// speedup vs baseline: 1.8200x; 1.5073x over previous
#include <cuda_runtime.h>
#include <cuda_fp16.h>

#define BB 2
#define SS 2048
#define DD 256
#define HH 8
#define DHD 32

// Scratch (allocation-free: device globals)
__device__ __half g_q[BB*HH*SS*DHD];
__device__ __half g_k[BB*HH*SS*DHD];
__device__ __half g_v[BB*HH*SS*DHD];
__device__ __half g_ctx[BB*SS*DD];
__device__ __half g_xh[BB*SS*DD];        // x converted to fp16
__device__ __half g_wh[3*DD*DD];         // wq|wk|wv fp16
__device__ __half g_wch[DD*DD];          // wc fp16

// ---------------------------------------------------------------------------
// helpers
// ---------------------------------------------------------------------------
__device__ __forceinline__ void mma_f16(float c[4], const unsigned a[4],
                                        unsigned b0, unsigned b1) {
    asm volatile(
        "mma.sync.aligned.m16n8k16.row.col.f32.f16.f16.f32 "
        "{%0,%1,%2,%3},{%4,%5,%6,%7},{%8,%9},{%0,%1,%2,%3};"
        : "+f"(c[0]), "+f"(c[1]), "+f"(c[2]), "+f"(c[3])
        : "r"(a[0]), "r"(a[1]), "r"(a[2]), "r"(a[3]), "r"(b0), "r"(b1));
}

__device__ __forceinline__ void ldsm_x2_t(unsigned& r0, unsigned& r1, const void* p) {
    unsigned addr = (unsigned)__cvta_generic_to_shared(p);
    asm volatile("ldmatrix.sync.aligned.m8n8.x2.trans.shared.b16 {%0,%1}, [%2];"
                 : "=r"(r0), "=r"(r1) : "r"(addr));
}

__device__ __forceinline__ float2 h2f(unsigned u) {
    return __half22float2(*(__half2*)&u);
}

__device__ __forceinline__ void cp16(void* dst, const void* src) {
    unsigned d = (unsigned)__cvta_generic_to_shared(dst);
    asm volatile("cp.async.cg.shared.global [%0], [%1], 16;" :: "r"(d), "l"(src));
}
#define CP_COMMIT() asm volatile("cp.async.commit_group;")
#define CP_WAIT1()  asm volatile("cp.async.wait_group 1;")
#define CP_WAIT0()  asm volatile("cp.async.wait_group 0;")

// ---------------------------------------------------------------------------
// fp32 -> fp16 conversion prologue (x, wq, wk, wv, wc)
// ---------------------------------------------------------------------------
__global__ __launch_bounds__(256) void convert_kernel(
    const float* __restrict__ x,
    const float* __restrict__ wq, const float* __restrict__ wk,
    const float* __restrict__ wv, const float* __restrict__ wc)
{
    int t = blockIdx.x * 256 + threadIdx.x;
    int e = t * 4;
    const float* src;
    __half* dst;
    if (e < BB*SS*DD) {
        src = x + e; dst = g_xh + e;
    } else {
        int r = e - BB*SS*DD;          // 0..262143
        int wsel = r >> 16;            // 0..3
        int off = r & 65535;
        src = (wsel == 0 ? wq : wsel == 1 ? wk : wsel == 2 ? wv : wc) + off;
        dst = (wsel == 3 ? g_wch : g_wh + wsel * 65536) + off;
    }
    float4 v = *(const float4*)src;
    __half2* d2 = (__half2*)dst;
    d2[0] = __floats2half2_rn(v.x, v.y);
    d2[1] = __floats2half2_rn(v.z, v.w);
}

// ---------------------------------------------------------------------------
// fp16 GEMM staging for the projections: CTA tile M=64, N=128, k-chunk 32.
// smem rows padded to 40 halfs (conflict-free 32-bit fragment loads).
// ---------------------------------------------------------------------------
__device__ __forceinline__ void stage_gemm(const __half* A, const __half* B,
                                           __half* As, __half* Bs,
                                           int mt0, int nbase, int c, int tid)
{
    {   int row = tid >> 2, seg = tid & 3;   // A: 64 rows
        cp16(As + row * 40 + seg * 8, A + (size_t)(mt0 + row) * 256 + c * 32 + seg * 8); }
    #pragma unroll
    for (int i = 0; i < 2; i++) {            // B: 128 rows
        int id = i * 256 + tid;
        int row = id >> 2, seg = id & 3;
        cp16(Bs + row * 40 + seg * 8, B + (size_t)(nbase + row) * 256 + c * 32 + seg * 8);
    }
    CP_COMMIT();
}

// ---------------------------------------------------------------------------
// QKV projection via fp16 mma: [4096,256] @ W^T[256,256] x3, fp16 head-major out.
// grid (64, 6): y>>1 selects q/k/v, y&1 selects n-half.
// ---------------------------------------------------------------------------
__global__ __launch_bounds__(256, 2) void qkv_mma_kernel(
    const float* __restrict__ bq, const float* __restrict__ bk,
    const float* __restrict__ bv)
{
    __shared__ __half As[2][64*40];
    __shared__ __half Bs[2][128*40];
    const int tid = threadIdx.x, w = tid >> 5, lane = tid & 31;
    const int g = lane >> 2, tg = lane & 3;
    const int warpM = w >> 2, warpN = w & 3;
    const int mt0 = blockIdx.x * 64;
    const int y = blockIdx.y;
    const int wsel = y >> 1;
    const int nbase = (y & 1) * 128;
    const __half* Bw = g_wh + wsel * DD * DD;
    const float* bias = wsel == 0 ? bq : (wsel == 1 ? bk : bv);
    __half* dst = wsel == 0 ? g_q : (wsel == 1 ? g_k : g_v);

    float acc[2][4][4] = {};

    stage_gemm(g_xh, Bw, As[0], Bs[0], mt0, nbase, 0, tid);
    stage_gemm(g_xh, Bw, As[1], Bs[1], mt0, nbase, 1, tid);
    for (int c = 0; c < 8; c++) {
        if (c < 7) CP_WAIT1(); else CP_WAIT0();
        __syncthreads();
        const __half* Ab = As[c & 1];
        const __half* Bb = Bs[c & 1];
        #pragma unroll
        for (int ks = 0; ks < 2; ks++) {
            unsigned a[2][4], bf[4][2];
            #pragma unroll
            for (int mt = 0; mt < 2; mt++) {
                const __half* ar  = Ab + (warpM*32 + mt*16 + g) * 40 + ks*16 + 2*tg;
                const __half* ar8 = ar + 8 * 40;
                a[mt][0] = *(const unsigned*)ar;       a[mt][1] = *(const unsigned*)ar8;
                a[mt][2] = *(const unsigned*)(ar + 8); a[mt][3] = *(const unsigned*)(ar8 + 8);
            }
            #pragma unroll
            for (int nt = 0; nt < 4; nt++) {
                const __half* br = Bb + (warpN*32 + nt*8 + g) * 40 + ks*16 + 2*tg;
                bf[nt][0] = *(const unsigned*)br;
                bf[nt][1] = *(const unsigned*)(br + 8);
            }
            #pragma unroll
            for (int mt = 0; mt < 2; mt++)
                #pragma unroll
                for (int nt = 0; nt < 4; nt++)
                    mma_f16(acc[mt][nt], a[mt], bf[nt][0], bf[nt][1]);
        }
        __syncthreads();
        if (c + 2 < 8) stage_gemm(g_xh, Bw, As[c & 1], Bs[c & 1], mt0, nbase, c + 2, tid);
    }

    #pragma unroll
    for (int mt = 0; mt < 2; mt++)
        #pragma unroll
        for (int hf = 0; hf < 2; hf++) {
            int m = mt0 + warpM*32 + mt*16 + g + hf*8;
            int bidx = m >> 11, s = m & 2047;
            #pragma unroll
            for (int nt = 0; nt < 4; nt++) {
                int n = nbase + warpN*32 + nt*8 + 2*tg;
                float c0 = acc[mt][nt][hf*2+0] + bias[n];
                float c1 = acc[mt][nt][hf*2+1] + bias[n+1];
                int h = n >> 5, dh = n & 31;
                *(__half2*)&dst[(((size_t)(bidx*HH + h) * SS + s) * DHD) + dh] =
                    __floats2half2_rn(c0, c1);
            }
        }
}

// ---------------------------------------------------------------------------
// Output projection via fp16 mma: out = ctx @ wc^T + bc (fp32 out).
// grid (64, 2).
// ---------------------------------------------------------------------------
__global__ __launch_bounds__(256, 2) void proj_mma_kernel(
    const float* __restrict__ bc, float* __restrict__ out)
{
    __shared__ __half As[2][64*40];
    __shared__ __half Bs[2][128*40];
    const int tid = threadIdx.x, w = tid >> 5, lane = tid & 31;
    const int g = lane >> 2, tg = lane & 3;
    const int warpM = w >> 2, warpN = w & 3;
    const int mt0 = blockIdx.x * 64;
    const int nbase = blockIdx.y * 128;

    float acc[2][4][4] = {};

    stage_gemm(g_ctx, g_wch, As[0], Bs[0], mt0, nbase, 0, tid);
    stage_gemm(g_ctx, g_wch, As[1], Bs[1], mt0, nbase, 1, tid);
    for (int c = 0; c < 8; c++) {
        if (c < 7) CP_WAIT1(); else CP_WAIT0();
        __syncthreads();
        const __half* Ab = As[c & 1];
        const __half* Bb = Bs[c & 1];
        #pragma unroll
        for (int ks = 0; ks < 2; ks++) {
            unsigned a[2][4], bf[4][2];
            #pragma unroll
            for (int mt = 0; mt < 2; mt++) {
                const __half* ar  = Ab + (warpM*32 + mt*16 + g) * 40 + ks*16 + 2*tg;
                const __half* ar8 = ar + 8 * 40;
                a[mt][0] = *(const unsigned*)ar;       a[mt][1] = *(const unsigned*)ar8;
                a[mt][2] = *(const unsigned*)(ar + 8); a[mt][3] = *(const unsigned*)(ar8 + 8);
            }
            #pragma unroll
            for (int nt = 0; nt < 4; nt++) {
                const __half* br = Bb + (warpN*32 + nt*8 + g) * 40 + ks*16 + 2*tg;
                bf[nt][0] = *(const unsigned*)br;
                bf[nt][1] = *(const unsigned*)(br + 8);
            }
            #pragma unroll
            for (int mt = 0; mt < 2; mt++)
                #pragma unroll
                for (int nt = 0; nt < 4; nt++)
                    mma_f16(acc[mt][nt], a[mt], bf[nt][0], bf[nt][1]);
        }
        __syncthreads();
        if (c + 2 < 8) stage_gemm(g_ctx, g_wch, As[c & 1], Bs[c & 1], mt0, nbase, c + 2, tid);
    }

    #pragma unroll
    for (int mt = 0; mt < 2; mt++)
        #pragma unroll
        for (int hf = 0; hf < 2; hf++) {
            int m = mt0 + warpM*32 + mt*16 + g + hf*8;
            #pragma unroll
            for (int nt = 0; nt < 4; nt++) {
                int n = nbase + warpN*32 + nt*8 + 2*tg;
                float c0 = acc[mt][nt][hf*2+0] + bc[n];
                float c1 = acc[mt][nt][hf*2+1] + bc[n+1];
                *(float2*)&out[(size_t)m * 256 + n] = make_float2(c0, c1);
            }
        }
}

// ---------------------------------------------------------------------------
// Attention v5: fp16 mma + cp.async double-buffered K/V staging.
// smem:
//   sS   [16][2056] fp16 = 65792  (scores/probs; tail aliased as sRd after PV)
//   buf0/buf1: 256 rows x 40 halfs = 20480B each (K/V tiles)
//   sQ   [16][40] fp16 = 1280        total 108032 -> 2 CTAs/SM
// ---------------------------------------------------------------------------
#define SSH 2056
#define SMEM_BYTES (16*SSH*2 + 2*20480 + 16*40*2)

__device__ __forceinline__ void stage_kv(const __half* src, __half* dst, int tid) {
    #pragma unroll
    for (int i = 0; i < 4; i++) {
        int id = i * 256 + tid;
        int row = id >> 2, seg = id & 3;
        cp16(dst + row * 40 + seg * 8, src + row * 32 + seg * 8);
    }
    CP_COMMIT();
}

__global__ __launch_bounds__(256, 2) void attn_kernel(float* __restrict__ attn_out)
{
    extern __shared__ char sm[];
    __half* sS = (__half*)sm;                         // 16 x 2056
    float*  sRd = (float*)sm;                         // aliases sS (dead at reduction)
    __half* buf0 = (__half*)(sm + 16 * SSH * 2);      // 256 x 40
    __half* buf1 = buf0 + 10240;                      // 256 x 40
    __half* sQ   = buf1 + 10240;                      // 16 x 40
    __shared__ float s_invl[16];

    const int tid  = threadIdx.x;
    const int w    = tid >> 5;
    const int lane = tid & 31;
    const int g    = lane >> 2;
    const int tg   = lane & 3;
    const int b  = blockIdx.x >> 7;
    const int q0 = (blockIdx.x & 127) << 4;

    float* ap = attn_out + (size_t)(b * SS + q0) * SS;

    // prefetch K tiles 0,1 of head 0
    {
        const __half* kb0 = g_k + (size_t)(b * HH) * SS * DHD;
        stage_kv(kb0, buf0, tid);
        stage_kv(kb0 + 8192, buf1, tid);
    }

    for (int h = 0; h < HH; h++) {
        const __half* qb = g_q + ((size_t)(b * HH + h) * SS + q0) * DHD;
        const __half* kb = g_k + (size_t)(b * HH + h) * SS * DHD;
        const __half* vb = g_v + (size_t)(b * HH + h) * SS * DHD;
        const __half* kbn = g_k + (size_t)(b * HH + ((h + 1) & 7)) * SS * DHD;

        // --- Q tile (16x32), scale by 1/sqrt(32) ---
        const float scale = 0.17677669529663687f;
        {
            int r = tid >> 4, c2 = (tid & 15) * 2;
            float2 f = __half22float2(*(const __half2*)(qb + r * 32 + c2));
            *(__half2*)(sQ + r * 40 + c2) = __floats2half2_rn(f.x * scale, f.y * scale);
        }

        // --- scores: 8 tiles of 256 keys, double-buffered ---
        unsigned qa[2][4];
        for (int kt = 0; kt < 8; kt++) {
            CP_WAIT1();
            __syncthreads();
            const __half* sK = (kt & 1) ? buf1 : buf0;
            if (kt == 0) {
                #pragma unroll
                for (int kc = 0; kc < 2; kc++) {
                    qa[kc][0] = *(const unsigned*)(sQ + g * 40 + kc * 16 + 2 * tg);
                    qa[kc][1] = *(const unsigned*)(sQ + (g + 8) * 40 + kc * 16 + 2 * tg);
                    qa[kc][2] = *(const unsigned*)(sQ + g * 40 + kc * 16 + 2 * tg + 8);
                    qa[kc][3] = *(const unsigned*)(sQ + (g + 8) * 40 + kc * 16 + 2 * tg + 8);
                }
            }
            #pragma unroll
            for (int nt = 0; nt < 4; nt++) {
                const int n0 = w * 32 + nt * 8;
                const __half* krow = sK + (n0 + g) * 40;
                float c[4] = {0.f, 0.f, 0.f, 0.f};
                #pragma unroll
                for (int kc = 0; kc < 2; kc++) {
                    unsigned b0 = *(const unsigned*)(krow + kc * 16 + 2 * tg);
                    unsigned b1 = *(const unsigned*)(krow + kc * 16 + 2 * tg + 8);
                    mma_f16(c, qa[kc], b0, b1);
                }
                const int col = kt * 256 + n0 + tg * 2;
                *(__half2*)(sS + g * SSH + col)       = __floats2half2_rn(c[0], c[1]);
                *(__half2*)(sS + (g + 8) * SSH + col) = __floats2half2_rn(c[2], c[3]);
            }
            __syncthreads();
            if (kt < 6)      stage_kv(kb + (size_t)(kt + 2) * 8192, (kt & 1) ? buf1 : buf0, tid);
            else if (kt == 6) stage_kv(vb, buf0, tid);
            else              stage_kv(vb + 8192, buf1, tid);
        }
        __syncthreads();

        // --- softmax (fp32 math, fp16 storage); V tiles 0,1 loading behind it ---
        {
            const int row = tid >> 4, j = tid & 15;
            uint4* r4 = (uint4*)(sS + (size_t)row * SSH);
            float mx = -1e30f;
            for (int k = j; k < 256; k += 16) {
                uint4 u = r4[k];
                float2 f0 = h2f(u.x), f1 = h2f(u.y), f2 = h2f(u.z), f3 = h2f(u.w);
                mx = fmaxf(mx, fmaxf(fmaxf(f0.x, f0.y), fmaxf(f1.x, f1.y)));
                mx = fmaxf(mx, fmaxf(fmaxf(f2.x, f2.y), fmaxf(f3.x, f3.y)));
            }
            #pragma unroll
            for (int o = 8; o; o >>= 1) mx = fmaxf(mx, __shfl_xor_sync(0xffffffffu, mx, o));
            float sum = 0.f;
            for (int k = j; k < 256; k += 16) {
                uint4 u = r4[k];
                float2 f0 = h2f(u.x), f1 = h2f(u.y), f2 = h2f(u.z), f3 = h2f(u.w);
                f0.x = __expf(f0.x - mx); f0.y = __expf(f0.y - mx);
                f1.x = __expf(f1.x - mx); f1.y = __expf(f1.y - mx);
                f2.x = __expf(f2.x - mx); f2.y = __expf(f2.y - mx);
                f3.x = __expf(f3.x - mx); f3.y = __expf(f3.y - mx);
                sum += (f0.x + f0.y) + (f1.x + f1.y) + (f2.x + f2.y) + (f3.x + f3.y);
                __half2 h0 = __floats2half2_rn(f0.x, f0.y);
                __half2 h1 = __floats2half2_rn(f1.x, f1.y);
                __half2 h2v = __floats2half2_rn(f2.x, f2.y);
                __half2 h3 = __floats2half2_rn(f3.x, f3.y);
                u.x = *(unsigned*)&h0; u.y = *(unsigned*)&h1;
                u.z = *(unsigned*)&h2v; u.w = *(unsigned*)&h3;
                r4[k] = u;
            }
            #pragma unroll
            for (int o = 8; o; o >>= 1) sum += __shfl_xor_sync(0xffffffffu, sum, o);
            if (j == 0) s_invl[row] = 1.0f / sum;
        }
        __syncthreads();

        // --- accumulate head-mean attention into d_out slice ---
        {
            float4* a4 = (float4*)ap;
            for (int t = tid; t < 16 * 512; t += 256) {
                int r = t >> 9, c4 = t & 511;
                uint2 u = *(const uint2*)(sS + (size_t)r * SSH + c4 * 4);
                float2 p0 = h2f(u.x), p1 = h2f(u.y);
                float f = s_invl[r] * 0.125f;
                float4 v = make_float4(p0.x * f, p0.y * f, p1.x * f, p1.y * f);
                if (h == 0) {
                    a4[r * 512 + c4] = v;
                } else {
                    float4 o = a4[r * 512 + c4];
                    o.x += v.x; o.y += v.y; o.z += v.z; o.w += v.w;
                    a4[r * 512 + c4] = o;
                }
            }
        }

        // --- PV: 8 phases of 256 k, double-buffered; warp owns k-slice w*32..+31 ---
        float oc[4][4] = {};
        for (int p = 0; p < 8; p++) {
            CP_WAIT1();
            __syncthreads();
            const __half* sVh = (p & 1) ? buf1 : buf0;
            #pragma unroll
            for (int j4 = 0; j4 < 2; j4++) {
                const int kr  = w * 32 + j4 * 16;
                const int ksg = p * 256 + kr;
                unsigned pa[4];
                pa[0] = *(const unsigned*)(sS + g * SSH + ksg + 2 * tg);
                pa[1] = *(const unsigned*)(sS + (g + 8) * SSH + ksg + 2 * tg);
                pa[2] = *(const unsigned*)(sS + g * SSH + ksg + 2 * tg + 8);
                pa[3] = *(const unsigned*)(sS + (g + 8) * SSH + ksg + 2 * tg + 8);
                const __half* vrow = sVh + (kr + (lane & 15)) * 40;
                #pragma unroll
                for (int nt = 0; nt < 4; nt++) {
                    unsigned b0, b1;
                    ldsm_x2_t(b0, b1, vrow + nt * 8);
                    mma_f16(oc[nt], pa, b0, b1);
                }
            }
            __syncthreads();
            if (p < 6)       stage_kv(vb + (size_t)(p + 2) * 8192, (p & 1) ? buf1 : buf0, tid);
            else if (p == 6) stage_kv(kbn, buf0, tid);
            else             stage_kv(kbn + 8192, buf1, tid);
        }
        __syncthreads();   // PV consumers of sS done -> sRd may alias it

        // --- cross-warp reduction of the 8 k-partials (sRd aliases sS) ---
        #pragma unroll
        for (int nt = 0; nt < 4; nt++) {
            const int col = nt * 8 + tg * 2;
            sRd[w * 512 + g * 32 + col]           = oc[nt][0];
            sRd[w * 512 + g * 32 + col + 1]       = oc[nt][1];
            sRd[w * 512 + (g + 8) * 32 + col]     = oc[nt][2];
            sRd[w * 512 + (g + 8) * 32 + col + 1] = oc[nt][3];
        }
        __syncthreads();
        for (int o = tid; o < 512; o += 256) {
            int r = o >> 5, d = o & 31;
            float s = 0.f;
            #pragma unroll
            for (int e = 0; e < 8; e++) s += sRd[e * 512 + o];
            g_ctx[(size_t)(b * SS + q0 + r) * DD + h * DHD + d] = __float2half(s * s_invl[r]);
        }
        __syncthreads();   // protect sRd/sQ/sS before next head
    }
    CP_WAIT0();   // drain the (dummy) trailing prefetch before exit
}

// ---------------------------------------------------------------------------
extern "C" void kernel_launch(void* const* d_in, const int* in_sizes, int n_in,
                              void* d_out, int out_size)
{
    const float* x  = (const float*)d_in[0];
    const float* wq = (const float*)d_in[1];
    const float* bq = (const float*)d_in[2];
    const float* wk = (const float*)d_in[3];
    const float* bk = (const float*)d_in[4];
    const float* wv = (const float*)d_in[5];
    const float* bv = (const float*)d_in[6];
    const float* wc = (const float*)d_in[7];
    const float* bc = (const float*)d_in[8];

    float* out  = (float*)d_out;
    float* attn = out + (size_t)BB * SS * DD;

    convert_kernel<<<1280, 256>>>(x, wq, wk, wv, wc);
    qkv_mma_kernel<<<dim3(64, 6), 256>>>(bq, bk, bv);

    cudaFuncSetAttribute(attn_kernel,
                         cudaFuncAttributeMaxDynamicSharedMemorySize,
                         SMEM_BYTES);
    attn_kernel<<<256, 256, SMEM_BYTES>>>(attn);

    proj_mma_kernel<<<dim3(64, 2), 256>>>(bc, out);
}

// round 15
// speedup vs baseline: 2.0789x; 1.1422x over previous
#include <cuda_runtime.h>
#include <cuda_fp16.h>

#define BB 2
#define SS 2048
#define DD 256
#define HH 8
#define DHD 32

// Scratch (allocation-free: device globals)
__device__ __half g_q[BB*HH*SS*DHD];
__device__ __half g_k[BB*HH*SS*DHD];
__device__ __half g_v[BB*HH*SS*DHD];
__device__ __half g_ctx[BB*SS*DD];
__device__ __half g_xh[BB*SS*DD];        // x converted to fp16
__device__ __half g_wh[3*DD*DD];         // wq|wk|wv fp16
__device__ __half g_wch[DD*DD];          // wc fp16

// ---------------------------------------------------------------------------
// helpers
// ---------------------------------------------------------------------------
__device__ __forceinline__ void mma_f16(float c[4], const unsigned a[4],
                                        unsigned b0, unsigned b1) {
    asm volatile(
        "mma.sync.aligned.m16n8k16.row.col.f32.f16.f16.f32 "
        "{%0,%1,%2,%3},{%4,%5,%6,%7},{%8,%9},{%0,%1,%2,%3};"
        : "+f"(c[0]), "+f"(c[1]), "+f"(c[2]), "+f"(c[3])
        : "r"(a[0]), "r"(a[1]), "r"(a[2]), "r"(a[3]), "r"(b0), "r"(b1));
}

__device__ __forceinline__ void ldsm_x2_t(unsigned& r0, unsigned& r1, const void* p) {
    unsigned addr = (unsigned)__cvta_generic_to_shared(p);
    asm volatile("ldmatrix.sync.aligned.m8n8.x2.trans.shared.b16 {%0,%1}, [%2];"
                 : "=r"(r0), "=r"(r1) : "r"(addr));
}

__device__ __forceinline__ float2 h2f(unsigned u) {
    return __half22float2(*(__half2*)&u);
}

__device__ __forceinline__ void cp16(void* dst, const void* src) {
    unsigned d = (unsigned)__cvta_generic_to_shared(dst);
    asm volatile("cp.async.cg.shared.global [%0], [%1], 16;" :: "r"(d), "l"(src));
}
#define CP_COMMIT() asm volatile("cp.async.commit_group;")
#define CP_WAIT1()  asm volatile("cp.async.wait_group 1;")
#define CP_WAIT0()  asm volatile("cp.async.wait_group 0;")

// ---------------------------------------------------------------------------
// fp32 -> fp16 conversion prologue (x, wq, wk, wv, wc)
// ---------------------------------------------------------------------------
__global__ __launch_bounds__(256) void convert_kernel(
    const float* __restrict__ x,
    const float* __restrict__ wq, const float* __restrict__ wk,
    const float* __restrict__ wv, const float* __restrict__ wc)
{
    int t = blockIdx.x * 256 + threadIdx.x;
    int e = t * 4;
    const float* src;
    __half* dst;
    if (e < BB*SS*DD) {
        src = x + e; dst = g_xh + e;
    } else {
        int r = e - BB*SS*DD;
        int wsel = r >> 16;
        int off = r & 65535;
        src = (wsel == 0 ? wq : wsel == 1 ? wk : wsel == 2 ? wv : wc) + off;
        dst = (wsel == 3 ? g_wch : g_wh + wsel * 65536) + off;
    }
    float4 v = *(const float4*)src;
    __half2* d2 = (__half2*)dst;
    d2[0] = __floats2half2_rn(v.x, v.y);
    d2[1] = __floats2half2_rn(v.z, v.w);
}

// ---------------------------------------------------------------------------
// fp16 GEMM staging for the projections: CTA tile M=64, N=128, k-chunk 32.
// ---------------------------------------------------------------------------
__device__ __forceinline__ void stage_gemm(const __half* A, const __half* B,
                                           __half* As, __half* Bs,
                                           int mt0, int nbase, int c, int tid)
{
    {   int row = tid >> 2, seg = tid & 3;
        cp16(As + row * 40 + seg * 8, A + (size_t)(mt0 + row) * 256 + c * 32 + seg * 8); }
    #pragma unroll
    for (int i = 0; i < 2; i++) {
        int id = i * 256 + tid;
        int row = id >> 2, seg = id & 3;
        cp16(Bs + row * 40 + seg * 8, B + (size_t)(nbase + row) * 256 + c * 32 + seg * 8);
    }
    CP_COMMIT();
}

// ---------------------------------------------------------------------------
// QKV projection via fp16 mma
// ---------------------------------------------------------------------------
__global__ __launch_bounds__(256, 2) void qkv_mma_kernel(
    const float* __restrict__ bq, const float* __restrict__ bk,
    const float* __restrict__ bv)
{
    __shared__ __half As[2][64*40];
    __shared__ __half Bs[2][128*40];
    const int tid = threadIdx.x, w = tid >> 5, lane = tid & 31;
    const int g = lane >> 2, tg = lane & 3;
    const int warpM = w >> 2, warpN = w & 3;
    const int mt0 = blockIdx.x * 64;
    const int y = blockIdx.y;
    const int wsel = y >> 1;
    const int nbase = (y & 1) * 128;
    const __half* Bw = g_wh + wsel * DD * DD;
    const float* bias = wsel == 0 ? bq : (wsel == 1 ? bk : bv);
    __half* dst = wsel == 0 ? g_q : (wsel == 1 ? g_k : g_v);

    float acc[2][4][4] = {};

    stage_gemm(g_xh, Bw, As[0], Bs[0], mt0, nbase, 0, tid);
    stage_gemm(g_xh, Bw, As[1], Bs[1], mt0, nbase, 1, tid);
    for (int c = 0; c < 8; c++) {
        if (c < 7) CP_WAIT1(); else CP_WAIT0();
        __syncthreads();
        const __half* Ab = As[c & 1];
        const __half* Bb = Bs[c & 1];
        #pragma unroll
        for (int ks = 0; ks < 2; ks++) {
            unsigned a[2][4], bf[4][2];
            #pragma unroll
            for (int mt = 0; mt < 2; mt++) {
                const __half* ar  = Ab + (warpM*32 + mt*16 + g) * 40 + ks*16 + 2*tg;
                const __half* ar8 = ar + 8 * 40;
                a[mt][0] = *(const unsigned*)ar;       a[mt][1] = *(const unsigned*)ar8;
                a[mt][2] = *(const unsigned*)(ar + 8); a[mt][3] = *(const unsigned*)(ar8 + 8);
            }
            #pragma unroll
            for (int nt = 0; nt < 4; nt++) {
                const __half* br = Bb + (warpN*32 + nt*8 + g) * 40 + ks*16 + 2*tg;
                bf[nt][0] = *(const unsigned*)br;
                bf[nt][1] = *(const unsigned*)(br + 8);
            }
            #pragma unroll
            for (int mt = 0; mt < 2; mt++)
                #pragma unroll
                for (int nt = 0; nt < 4; nt++)
                    mma_f16(acc[mt][nt], a[mt], bf[nt][0], bf[nt][1]);
        }
        __syncthreads();
        if (c + 2 < 8) stage_gemm(g_xh, Bw, As[c & 1], Bs[c & 1], mt0, nbase, c + 2, tid);
    }

    #pragma unroll
    for (int mt = 0; mt < 2; mt++)
        #pragma unroll
        for (int hf = 0; hf < 2; hf++) {
            int m = mt0 + warpM*32 + mt*16 + g + hf*8;
            int bidx = m >> 11, s = m & 2047;
            #pragma unroll
            for (int nt = 0; nt < 4; nt++) {
                int n = nbase + warpN*32 + nt*8 + 2*tg;
                float c0 = acc[mt][nt][hf*2+0] + bias[n];
                float c1 = acc[mt][nt][hf*2+1] + bias[n+1];
                int h = n >> 5, dh = n & 31;
                *(__half2*)&dst[(((size_t)(bidx*HH + h) * SS + s) * DHD) + dh] =
                    __floats2half2_rn(c0, c1);
            }
        }
}

// ---------------------------------------------------------------------------
// Output projection via fp16 mma
// ---------------------------------------------------------------------------
__global__ __launch_bounds__(256, 2) void proj_mma_kernel(
    const float* __restrict__ bc, float* __restrict__ out)
{
    __shared__ __half As[2][64*40];
    __shared__ __half Bs[2][128*40];
    const int tid = threadIdx.x, w = tid >> 5, lane = tid & 31;
    const int g = lane >> 2, tg = lane & 3;
    const int warpM = w >> 2, warpN = w & 3;
    const int mt0 = blockIdx.x * 64;
    const int nbase = blockIdx.y * 128;

    float acc[2][4][4] = {};

    stage_gemm(g_ctx, g_wch, As[0], Bs[0], mt0, nbase, 0, tid);
    stage_gemm(g_ctx, g_wch, As[1], Bs[1], mt0, nbase, 1, tid);
    for (int c = 0; c < 8; c++) {
        if (c < 7) CP_WAIT1(); else CP_WAIT0();
        __syncthreads();
        const __half* Ab = As[c & 1];
        const __half* Bb = Bs[c & 1];
        #pragma unroll
        for (int ks = 0; ks < 2; ks++) {
            unsigned a[2][4], bf[4][2];
            #pragma unroll
            for (int mt = 0; mt < 2; mt++) {
                const __half* ar  = Ab + (warpM*32 + mt*16 + g) * 40 + ks*16 + 2*tg;
                const __half* ar8 = ar + 8 * 40;
                a[mt][0] = *(const unsigned*)ar;       a[mt][1] = *(const unsigned*)ar8;
                a[mt][2] = *(const unsigned*)(ar + 8); a[mt][3] = *(const unsigned*)(ar8 + 8);
            }
            #pragma unroll
            for (int nt = 0; nt < 4; nt++) {
                const __half* br = Bb + (warpN*32 + nt*8 + g) * 40 + ks*16 + 2*tg;
                bf[nt][0] = *(const unsigned*)br;
                bf[nt][1] = *(const unsigned*)(br + 8);
            }
            #pragma unroll
            for (int mt = 0; mt < 2; mt++)
                #pragma unroll
                for (int nt = 0; nt < 4; nt++)
                    mma_f16(acc[mt][nt], a[mt], bf[nt][0], bf[nt][1]);
        }
        __syncthreads();
        if (c + 2 < 8) stage_gemm(g_ctx, g_wch, As[c & 1], Bs[c & 1], mt0, nbase, c + 2, tid);
    }

    #pragma unroll
    for (int mt = 0; mt < 2; mt++)
        #pragma unroll
        for (int hf = 0; hf < 2; hf++) {
            int m = mt0 + warpM*32 + mt*16 + g + hf*8;
            #pragma unroll
            for (int nt = 0; nt < 4; nt++) {
                int n = nbase + warpN*32 + nt*8 + 2*tg;
                float c0 = acc[mt][nt][hf*2+0] + bc[n];
                float c1 = acc[mt][nt][hf*2+1] + bc[n+1];
                *(float2*)&out[(size_t)m * 256 + n] = make_float2(c0, c1);
            }
        }
}

// ---------------------------------------------------------------------------
// Attention v6: 32-row q tiles, 512 threads, 1 CTA/SM, grid 128.
// Halves K/V re-read L2 traffic vs 16-row tiles.
// smem:
//   sS   [32][2056] fp16 = 131584  (scores/probs; aliased as sRd after PV)
//   buf0/buf1: 256 rows x 40 halfs = 20480B each
//   sQ   [32][40] fp16 = 2560        total 175104
// ---------------------------------------------------------------------------
#define SSH 2056
#define SMEM_BYTES (32*SSH*2 + 2*20480 + 32*40*2)

__device__ __forceinline__ void stage_kv(const __half* src, __half* dst, int tid) {
    #pragma unroll
    for (int i = 0; i < 2; i++) {
        int id = i * 512 + tid;
        int row = id >> 2, seg = id & 3;
        cp16(dst + row * 40 + seg * 8, src + row * 32 + seg * 8);
    }
    CP_COMMIT();
}

__global__ __launch_bounds__(512, 1) void attn_kernel(float* __restrict__ attn_out)
{
    extern __shared__ char sm[];
    __half* sS = (__half*)sm;                         // 32 x 2056
    float*  sRd = (float*)sm;                         // aliases sS (dead at reduction)
    __half* buf0 = (__half*)(sm + 32 * SSH * 2);      // 256 x 40
    __half* buf1 = buf0 + 10240;
    __half* sQ   = buf1 + 10240;                      // 32 x 40
    __shared__ float s_invl[32];

    const int tid  = threadIdx.x;
    const int w    = tid >> 5;       // warp 0..15
    const int lane = tid & 31;
    const int g    = lane >> 2;
    const int tg   = lane & 3;
    const int b  = blockIdx.x >> 6;
    const int q0 = (blockIdx.x & 63) << 5;

    float* ap = attn_out + (size_t)(b * SS + q0) * SS;

    // prefetch K tiles 0,1 of head 0
    {
        const __half* kb0 = g_k + (size_t)(b * HH) * SS * DHD;
        stage_kv(kb0, buf0, tid);
        stage_kv(kb0 + 8192, buf1, tid);
    }

    for (int h = 0; h < HH; h++) {
        const __half* qb = g_q + ((size_t)(b * HH + h) * SS + q0) * DHD;
        const __half* kb = g_k + (size_t)(b * HH + h) * SS * DHD;
        const __half* vb = g_v + (size_t)(b * HH + h) * SS * DHD;
        const __half* kbn = g_k + (size_t)(b * HH + ((h + 1) & 7)) * SS * DHD;

        // --- Q tile (32x32), scale by 1/sqrt(32) ---
        const float scale = 0.17677669529663687f;
        {
            int r = tid >> 4, c2 = (tid & 15) * 2;
            float2 f = __half22float2(*(const __half2*)(qb + r * 32 + c2));
            *(__half2*)(sQ + r * 40 + c2) = __floats2half2_rn(f.x * scale, f.y * scale);
        }

        // --- scores: 8 tiles of 256 keys; warp owns 16-key n-slice per tile ---
        unsigned qa[2][2][4];     // [mtile][kc][frag]
        for (int kt = 0; kt < 8; kt++) {
            CP_WAIT1();
            __syncthreads();
            const __half* sK = (kt & 1) ? buf1 : buf0;
            if (kt == 0) {
                #pragma unroll
                for (int mt = 0; mt < 2; mt++)
                    #pragma unroll
                    for (int kc = 0; kc < 2; kc++) {
                        const __half* qr  = sQ + (mt*16 + g) * 40 + kc * 16 + 2 * tg;
                        const __half* qr8 = qr + 8 * 40;
                        qa[mt][kc][0] = *(const unsigned*)qr;
                        qa[mt][kc][1] = *(const unsigned*)qr8;
                        qa[mt][kc][2] = *(const unsigned*)(qr + 8);
                        qa[mt][kc][3] = *(const unsigned*)(qr8 + 8);
                    }
            }
            #pragma unroll
            for (int nt = 0; nt < 2; nt++) {
                const int n0 = w * 16 + nt * 8;
                const __half* krow = sK + (n0 + g) * 40;
                unsigned b0[2], b1[2];
                #pragma unroll
                for (int kc = 0; kc < 2; kc++) {
                    b0[kc] = *(const unsigned*)(krow + kc * 16 + 2 * tg);
                    b1[kc] = *(const unsigned*)(krow + kc * 16 + 2 * tg + 8);
                }
                #pragma unroll
                for (int mt = 0; mt < 2; mt++) {
                    float c[4] = {0.f, 0.f, 0.f, 0.f};
                    #pragma unroll
                    for (int kc = 0; kc < 2; kc++)
                        mma_f16(c, qa[mt][kc], b0[kc], b1[kc]);
                    const int col = kt * 256 + n0 + tg * 2;
                    *(__half2*)(sS + (mt*16 + g) * SSH + col)     = __floats2half2_rn(c[0], c[1]);
                    *(__half2*)(sS + (mt*16 + g + 8) * SSH + col) = __floats2half2_rn(c[2], c[3]);
                }
            }
            __syncthreads();
            if (kt < 6)       stage_kv(kb + (size_t)(kt + 2) * 8192, (kt & 1) ? buf1 : buf0, tid);
            else if (kt == 6) stage_kv(vb, buf0, tid);
            else              stage_kv(vb + 8192, buf1, tid);
        }
        __syncthreads();

        // --- softmax (fp32 math, fp16 storage); V tiles 0,1 loading behind it ---
        {
            const int row = tid >> 4, j = tid & 15;   // 32 rows x 16 threads
            uint4* r4 = (uint4*)(sS + (size_t)row * SSH);
            float mx = -1e30f;
            for (int k = j; k < 256; k += 16) {
                uint4 u = r4[k];
                float2 f0 = h2f(u.x), f1 = h2f(u.y), f2 = h2f(u.z), f3 = h2f(u.w);
                mx = fmaxf(mx, fmaxf(fmaxf(f0.x, f0.y), fmaxf(f1.x, f1.y)));
                mx = fmaxf(mx, fmaxf(fmaxf(f2.x, f2.y), fmaxf(f3.x, f3.y)));
            }
            #pragma unroll
            for (int o = 8; o; o >>= 1) mx = fmaxf(mx, __shfl_xor_sync(0xffffffffu, mx, o));
            float sum = 0.f;
            for (int k = j; k < 256; k += 16) {
                uint4 u = r4[k];
                float2 f0 = h2f(u.x), f1 = h2f(u.y), f2 = h2f(u.z), f3 = h2f(u.w);
                f0.x = __expf(f0.x - mx); f0.y = __expf(f0.y - mx);
                f1.x = __expf(f1.x - mx); f1.y = __expf(f1.y - mx);
                f2.x = __expf(f2.x - mx); f2.y = __expf(f2.y - mx);
                f3.x = __expf(f3.x - mx); f3.y = __expf(f3.y - mx);
                sum += (f0.x + f0.y) + (f1.x + f1.y) + (f2.x + f2.y) + (f3.x + f3.y);
                __half2 h0 = __floats2half2_rn(f0.x, f0.y);
                __half2 h1 = __floats2half2_rn(f1.x, f1.y);
                __half2 h2v = __floats2half2_rn(f2.x, f2.y);
                __half2 h3 = __floats2half2_rn(f3.x, f3.y);
                u.x = *(unsigned*)&h0; u.y = *(unsigned*)&h1;
                u.z = *(unsigned*)&h2v; u.w = *(unsigned*)&h3;
                r4[k] = u;
            }
            #pragma unroll
            for (int o = 8; o; o >>= 1) sum += __shfl_xor_sync(0xffffffffu, sum, o);
            if (j == 0) s_invl[row] = 1.0f / sum;
        }
        __syncthreads();

        // --- accumulate head-mean attention into d_out slice ---
        {
            float4* a4 = (float4*)ap;
            for (int t = tid; t < 32 * 512; t += 512) {
                int r = t >> 9, c4 = t & 511;
                uint2 u = *(const uint2*)(sS + (size_t)r * SSH + c4 * 4);
                float2 p0 = h2f(u.x), p1 = h2f(u.y);
                float f = s_invl[r] * 0.125f;
                float4 v = make_float4(p0.x * f, p0.y * f, p1.x * f, p1.y * f);
                if (h == 0) {
                    a4[r * 512 + c4] = v;
                } else {
                    float4 o = a4[r * 512 + c4];
                    o.x += v.x; o.y += v.y; o.z += v.z; o.w += v.w;
                    a4[r * 512 + c4] = o;
                }
            }
        }

        // --- PV: 8 phases of 256 k; warp owns 16-key k-slice per phase ---
        float oc[2][4][4] = {};
        for (int p = 0; p < 8; p++) {
            CP_WAIT1();
            __syncthreads();
            const __half* sVh = (p & 1) ? buf1 : buf0;
            const int kr  = w * 16;
            const int ksg = p * 256 + kr;
            unsigned pa[2][4];
            #pragma unroll
            for (int mt = 0; mt < 2; mt++) {
                pa[mt][0] = *(const unsigned*)(sS + (mt*16 + g) * SSH + ksg + 2 * tg);
                pa[mt][1] = *(const unsigned*)(sS + (mt*16 + g + 8) * SSH + ksg + 2 * tg);
                pa[mt][2] = *(const unsigned*)(sS + (mt*16 + g) * SSH + ksg + 2 * tg + 8);
                pa[mt][3] = *(const unsigned*)(sS + (mt*16 + g + 8) * SSH + ksg + 2 * tg + 8);
            }
            const __half* vrow = sVh + (kr + (lane & 15)) * 40;
            #pragma unroll
            for (int nt = 0; nt < 4; nt++) {
                unsigned b0, b1;
                ldsm_x2_t(b0, b1, vrow + nt * 8);
                #pragma unroll
                for (int mt = 0; mt < 2; mt++)
                    mma_f16(oc[mt][nt], pa[mt], b0, b1);
            }
            __syncthreads();
            if (p < 6)       stage_kv(vb + (size_t)(p + 2) * 8192, (p & 1) ? buf1 : buf0, tid);
            else if (p == 6) stage_kv(kbn, buf0, tid);
            else             stage_kv(kbn + 8192, buf1, tid);
        }
        __syncthreads();   // PV consumers of sS done -> sRd may alias it

        // --- cross-warp reduction of the 16 k-partials (sRd aliases sS) ---
        #pragma unroll
        for (int mt = 0; mt < 2; mt++)
            #pragma unroll
            for (int nt = 0; nt < 4; nt++) {
                const int col = nt * 8 + tg * 2;
                sRd[w * 1024 + (mt*16 + g) * 32 + col]           = oc[mt][nt][0];
                sRd[w * 1024 + (mt*16 + g) * 32 + col + 1]       = oc[mt][nt][1];
                sRd[w * 1024 + (mt*16 + g + 8) * 32 + col]       = oc[mt][nt][2];
                sRd[w * 1024 + (mt*16 + g + 8) * 32 + col + 1]   = oc[mt][nt][3];
            }
        __syncthreads();
        for (int o = tid; o < 1024; o += 512) {
            int r = o >> 5, d = o & 31;
            float s = 0.f;
            #pragma unroll
            for (int e = 0; e < 16; e++) s += sRd[e * 1024 + o];
            g_ctx[(size_t)(b * SS + q0 + r) * DD + h * DHD + d] = __float2half(s * s_invl[r]);
        }
        __syncthreads();   // protect sRd/sQ/sS before next head
    }
    CP_WAIT0();   // drain trailing (dummy) prefetch before exit
}

// ---------------------------------------------------------------------------
extern "C" void kernel_launch(void* const* d_in, const int* in_sizes, int n_in,
                              void* d_out, int out_size)
{
    const float* x  = (const float*)d_in[0];
    const float* wq = (const float*)d_in[1];
    const float* bq = (const float*)d_in[2];
    const float* wk = (const float*)d_in[3];
    const float* bk = (const float*)d_in[4];
    const float* wv = (const float*)d_in[5];
    const float* bv = (const float*)d_in[6];
    const float* wc = (const float*)d_in[7];
    const float* bc = (const float*)d_in[8];

    float* out  = (float*)d_out;
    float* attn = out + (size_t)BB * SS * DD;

    convert_kernel<<<1280, 256>>>(x, wq, wk, wv, wc);
    qkv_mma_kernel<<<dim3(64, 6), 256>>>(bq, bk, bv);

    cudaFuncSetAttribute(attn_kernel,
                         cudaFuncAttributeMaxDynamicSharedMemorySize,
                         SMEM_BYTES);
    attn_kernel<<<128, 512, SMEM_BYTES>>>(attn);

    proj_mma_kernel<<<dim3(64, 2), 256>>>(bc, out);
}